// round 15
// baseline (speedup 1.0000x reference)
#include <cuda_runtime.h>
#include <math.h>

#define NN 50000
#define EE 800000
#define FF 128
#define HH 128
#define HID2 64
#define TT 8
#define GG 64

typedef unsigned long long u64;

// ---------------- scratch (device globals; no allocations allowed) ----------
__device__ __align__(16) int   g_cnt[NN];        // in-degree (excl self-loop)
__device__ __align__(16) int   g_base[NN];       // CSR row start
__device__ __align__(16) int   g_cur[NN];        // fill cursor
__device__ __align__(16) int   g_es[EE];         // edge sources grouped by dst
__device__ __align__(16) int   g_bsum[256];      // scan partials
__device__ __align__(16) int   g_boff[256];      // scan block offsets
__device__ __align__(16) float g_dinv[NN];       // (deg+1)^-1/2
__device__ __align__(16) float g_g[NN * HH];     // g = (x@W) * dinv[row]
__device__ __align__(16) float g_sums[GG * HH];  // pooled sums per graph
__device__ __align__(16) float g_cnts[GG];       // node counts per graph

// ---------------- f32x2 packed helpers (sm_100+) -----------------------------
__device__ __forceinline__ u64 ffma2(u64 a, u64 b, u64 c) {
    u64 d;
    asm("fma.rn.f32x2 %0, %1, %2, %3;" : "=l"(d) : "l"(a), "l"(b), "l"(c));
    return d;
}
__device__ __forceinline__ u64 pack2(float x) {
    u64 d;
    asm("mov.b64 %0, {%1, %1};" : "=l"(d) : "f"(x));
    return d;
}
__device__ __forceinline__ float2 unpack2(u64 v) {
    float2 r;
    asm("mov.b64 {%0, %1}, %2;" : "=f"(r.x), "=f"(r.y) : "l"(v));
    return r;
}

// ---------------- zero counters ---------------------------------------------
__global__ void k_zero(int n) {
    int i = blockIdx.x * blockDim.x + threadIdx.x;
    if (i < n) g_cnt[i] = 0;
    if (i < GG * HH) g_sums[i] = 0.0f;
    if (i < GG) g_cnts[i] = 0.0f;
}

// ---------------- in-degree histogram over destinations ---------------------
__global__ void k_count(const int* __restrict__ dst, int e) {
    int i = blockIdx.x * blockDim.x + threadIdx.x;
    if (i < e) atomicAdd(&g_cnt[__ldg(&dst[i])], 1);
}

// ---------------- two-level exclusive scan ----------------------------------
__global__ void k_scan1(int n) {
    __shared__ int sh[256];
    const int t = threadIdx.x;
    const int i = blockIdx.x * 256 + t;
    int v = (i < n) ? g_cnt[i] : 0;
    sh[t] = v;
    __syncthreads();
#pragma unroll
    for (int off = 1; off < 256; off <<= 1) {
        int add = (t >= off) ? sh[t - off] : 0;
        __syncthreads();
        sh[t] += add;
        __syncthreads();
    }
    if (i < n) g_base[i] = sh[t] - v;      // exclusive within block
    if (t == 255) g_bsum[blockIdx.x] = sh[255];
}

__global__ void k_scan2(int nb) {
    __shared__ int sh[256];
    const int t = threadIdx.x;
    int v = (t < nb) ? g_bsum[t] : 0;
    sh[t] = v;
    __syncthreads();
#pragma unroll
    for (int off = 1; off < 256; off <<= 1) {
        int add = (t >= off) ? sh[t - off] : 0;
        __syncthreads();
        sh[t] += add;
        __syncthreads();
    }
    if (t < nb) g_boff[t] = sh[t] - v;
}

// also computes dinv and per-graph node counts
__global__ void k_scan3(const int* __restrict__ batch, int n) {
    int i = blockIdx.x * blockDim.x + threadIdx.x;
    if (i < n) {
        int b = g_base[i] + g_boff[i >> 8];
        g_base[i] = b;
        g_cur[i]  = b;
        g_dinv[i] = rsqrtf((float)g_cnt[i] + 1.0f);   // +1 self-loop
        atomicAdd(&g_cnts[__ldg(&batch[i])], 1.0f);
    }
}

// ---------------- fill CSR edge array ----------------------------------------
__global__ void k_fill(const int* __restrict__ src, const int* __restrict__ dst, int e) {
    int i = blockIdx.x * blockDim.x + threadIdx.x;
    if (i < e) {
        int d = __ldg(&dst[i]);
        int pos = atomicAdd(&g_cur[d], 1);
        g_es[pos] = __ldg(&src[i]);
    }
}

// ---------------- GEMM: g = (x @ W) * dinv[row] ------------------------------
// 64 rows x 128 cols per block, 256 threads, 8x4 register tile (as 8x2 f32x2),
// K-chunk 32, packed fma.rn.f32x2 for 2x fp32 rate.
__global__ __launch_bounds__(256) void k_gemm(const float* __restrict__ x,
                                              const float* __restrict__ W,
                                              int n) {
    __shared__ float Ws[32][HH];   // 16 KB
    __shared__ float Xs[64][32];   // 8 KB

    const int tid  = threadIdx.x;
    const int row0 = blockIdx.x * 64;
    const int cg   = tid & 31;     // cols cg*4 .. cg*4+3
    const int rg   = tid >> 5;     // rows rg*8 .. rg*8+7

    u64 acc2[8][2];
#pragma unroll
    for (int r = 0; r < 8; r++) { acc2[r][0] = 0ULL; acc2[r][1] = 0ULL; }

    for (int kt = 0; kt < FF; kt += 32) {
        // stage X tile: 512 float4, 2 per thread
#pragma unroll
        for (int i = 0; i < 2; i++) {
            int f4 = tid + i * 256;
            int xr = f4 >> 3;            // 0..63
            int xq = f4 & 7;             // 0..7
            float4 v = make_float4(0.f, 0.f, 0.f, 0.f);
            int grow = row0 + xr;
            if (grow < n)
                v = *(const float4*)(x + (size_t)grow * FF + kt + xq * 4);
            *(float4*)&Xs[xr][xq * 4] = v;
        }
        // stage W tile: 1024 float4, 4 per thread
#pragma unroll
        for (int i = 0; i < 4; i++) {
            int f4 = tid + i * 256;
            int kk = f4 >> 5;            // 0..31
            int j4 = f4 & 31;            // 0..31
            *(float4*)&Ws[kk][j4 * 4] =
                *(const float4*)(W + (size_t)(kt + kk) * HH + j4 * 4);
        }
        __syncthreads();

#pragma unroll
        for (int kk = 0; kk < 32; kk++) {
            ulonglong2 wv = *(const ulonglong2*)&Ws[kk][cg * 4];  // cols as 2x f32x2
#pragma unroll
            for (int r = 0; r < 8; r++) {
                u64 xx = pack2(Xs[rg * 8 + r][kk]);   // {xv, xv}
                acc2[r][0] = ffma2(xx, wv.x, acc2[r][0]);
                acc2[r][1] = ffma2(xx, wv.y, acc2[r][1]);
            }
        }
        __syncthreads();
    }

#pragma unroll
    for (int r = 0; r < 8; r++) {
        int row = row0 + rg * 8 + r;
        if (row < n) {
            float s = g_dinv[row];
            float2 lo = unpack2(acc2[r][0]);
            float2 hi = unpack2(acc2[r][1]);
            float4 v = make_float4(lo.x * s, lo.y * s, hi.x * s, hi.y * s);
            *(float4*)(g_g + (size_t)row * HH + cg * 4) = v;
        }
    }
}

// ---------------- CSR gather + fused relu/bias + fused mean-pool sum ---------
// One warp per dst node; lane handles 4 cols. h = relu(dinv*(g_self+sum)+b),
// then h is atomically accumulated into g_sums[batch[node]].
__global__ __launch_bounds__(256) void k_gather(const float* __restrict__ bias,
                                                const int* __restrict__ batch) {
    const int wid  = (blockIdx.x * 256 + threadIdx.x) >> 5;
    const int lane = threadIdx.x & 31;
    if (wid >= NN) return;

    const float4* __restrict__ gp = (const float4*)g_g;
    float4 acc = __ldg(gp + (size_t)wid * 32 + lane);   // self-loop term

    const int b0  = g_base[wid];
    const int end = b0 + g_cnt[wid];
    int k = b0;
    for (; k + 8 <= end; k += 8) {
        int s[8];
#pragma unroll
        for (int u = 0; u < 8; u++) s[u] = __ldg(&g_es[k + u]);
        float4 a[8];
#pragma unroll
        for (int u = 0; u < 8; u++) a[u] = __ldg(gp + (size_t)s[u] * 32 + lane);
        float4 p0, p1;
        p0.x = (a[0].x + a[1].x) + (a[2].x + a[3].x);
        p0.y = (a[0].y + a[1].y) + (a[2].y + a[3].y);
        p0.z = (a[0].z + a[1].z) + (a[2].z + a[3].z);
        p0.w = (a[0].w + a[1].w) + (a[2].w + a[3].w);
        p1.x = (a[4].x + a[5].x) + (a[6].x + a[7].x);
        p1.y = (a[4].y + a[5].y) + (a[6].y + a[7].y);
        p1.z = (a[4].z + a[5].z) + (a[6].z + a[7].z);
        p1.w = (a[4].w + a[5].w) + (a[6].w + a[7].w);
        acc.x += p0.x + p1.x;
        acc.y += p0.y + p1.y;
        acc.z += p0.z + p1.z;
        acc.w += p0.w + p1.w;
    }
    for (; k < end; k++) {
        int s = __ldg(&g_es[k]);
        float4 a = __ldg(gp + (size_t)s * 32 + lane);
        acc.x += a.x; acc.y += a.y; acc.z += a.z; acc.w += a.w;
    }

    const float dv = g_dinv[wid];
    const float4 bb = __ldg((const float4*)bias + lane);
    float4 h;
    h.x = fmaxf(acc.x * dv + bb.x, 0.0f);
    h.y = fmaxf(acc.y * dv + bb.y, 0.0f);
    h.z = fmaxf(acc.z * dv + bb.z, 0.0f);
    h.w = fmaxf(acc.w * dv + bb.w, 0.0f);

    const int bid = __ldg(&batch[wid]);
    float* sp = g_sums + (size_t)bid * HH + lane * 4;
    atomicAdd(sp + 0, h.x);
    atomicAdd(sp + 1, h.y);
    atomicAdd(sp + 2, h.z);
    atomicAdd(sp + 3, h.w);
}

// ---------------- head: fc1+relu, actor softmax, critic ----------------------
__global__ __launch_bounds__(128) void k_head(const float* __restrict__ fc1_w,
                                              const float* __restrict__ fc1_b,
                                              const float* __restrict__ aw,
                                              const float* __restrict__ ab,
                                              const float* __restrict__ cw,
                                              const float* __restrict__ cb,
                                              float* __restrict__ out) {
    const int g = blockIdx.x;
    const int t = threadIdx.x;
    __shared__ float st[HH];
    __shared__ float z[HID2];
    __shared__ float lg[TT];

    st[t] = g_sums[g * HH + t] / fmaxf(g_cnts[g], 1.0f);
    __syncthreads();

    if (t < HID2) {
        float a = fc1_b[t];
#pragma unroll 8
        for (int k = 0; k < HH; k++) a += st[k] * fc1_w[k * HID2 + t];
        z[t] = fmaxf(a, 0.0f);
    }
    __syncthreads();

    if (t < TT) {
        float a = ab[t];
#pragma unroll 8
        for (int k = 0; k < HID2; k++) a += z[k] * aw[k * TT + t];
        lg[t] = a;
    }
    if (t == 32) {
        float v = cb[0];
#pragma unroll 8
        for (int k = 0; k < HID2; k++) v += z[k] * cw[k];
        out[GG * TT + g] = v;
    }
    __syncthreads();

    if (t == 0) {
        float m = -1e30f;
#pragma unroll
        for (int i = 0; i < TT; i++) m = fmaxf(m, lg[i]);
        float ex[TT];
        float s = 0.0f;
#pragma unroll
        for (int i = 0; i < TT; i++) { ex[i] = __expf(lg[i] - m); s += ex[i]; }
        float inv = 1.0f / s;
#pragma unroll
        for (int i = 0; i < TT; i++) out[g * TT + i] = ex[i] * inv;
    }
}

// ---------------- launcher ----------------------------------------------------
extern "C" void kernel_launch(void* const* d_in, const int* in_sizes, int n_in,
                              void* d_out, int out_size) {
    const float* x     = (const float*)d_in[0];
    const int*   eidx  = (const int*)d_in[1];
    const int*   batch = (const int*)d_in[2];
    const float* W     = (const float*)d_in[3];
    const float* b     = (const float*)d_in[4];
    const float* fc1_w = (const float*)d_in[5];
    const float* fc1_b = (const float*)d_in[6];
    const float* aw    = (const float*)d_in[7];
    const float* ab    = (const float*)d_in[8];
    const float* cw    = (const float*)d_in[9];
    const float* cb    = (const float*)d_in[10];
    float* out = (float*)d_out;

    const int n = in_sizes[0] / FF;   // 50000
    const int e = in_sizes[1] / 2;    // 800000
    const int* src = eidx;
    const int* dst = eidx + e;
    const int nb = (n + 255) / 256;   // scan blocks (196 <= 256)

    k_zero<<<(n + 255) / 256, 256>>>(n);
    k_count<<<(e + 255) / 256, 256>>>(dst, e);
    k_scan1<<<nb, 256>>>(n);
    k_scan2<<<1, 256>>>(nb);
    k_scan3<<<(n + 255) / 256, 256>>>(batch, n);
    k_fill<<<(e + 255) / 256, 256>>>(src, dst, e);
    k_gemm<<<(n + 63) / 64, 256>>>(x, W, n);
    k_gather<<<(NN * 32 + 255) / 256, 256>>>(b, batch);
    k_head<<<GG, 128>>>(fc1_w, fc1_b, aw, ab, cw, cb, out);
}